// round 13
// baseline (speedup 1.0000x reference)
#include <cuda_runtime.h>

#define BB 16
#define KK 512
#define DD 256
#define TT 4096
#define TTILE 128          // frames per block
#define DHALF 128          // d-rows per block (D split over grid.z)
#define NWARP 8
#define THREADS 256
#define DPW (DHALF / NWARP)  // 16 d-rows per warp
#define SPAN 64            // max block k-range staged
#define SPANP 80           // sPh row pitch: SPAN + WMAX zero-pad
#define WMAX 16            // max weight slots per quad-union window
#define WP 132             // sW row pitch (floats): 16B multiple + bank offset
#define THRESH 25.0f       // keep terms with weight ratio > e^-25

__global__ void __launch_bounds__(THREADS, 4) fused_upsample_kernel(
    const float* __restrict__ durations,  // (B, K)
    const float* __restrict__ phoneme,    // (B, D, K)
    const float* __restrict__ frame,      // (B, D, T)
    float* __restrict__ out)              // (B, D, T)
{
    extern __shared__ __align__(16) float sm[];
    float* sC  = sm;                              // KK centers
    float* sW  = sC + KK;                         // WMAX * WP   ([union j][t] weights)
    float* sPh = sW + WMAX * WP;                  // DHALF * SPANP (also cumsum scratch)
    int* sQ    = (int*)(sPh + DHALF * SPANP);     // TTILE/4 quad base (absolute kmn)
    int* sUW   = sQ + TTILE / 4;                  // TTILE/4 quad union width
    int* sKb   = sUW + TTILE / 4;                 // 2

    const int b     = blockIdx.y;
    const int t0    = blockIdx.x * TTILE;
    const int dbase = blockIdx.z * DHALF;
    const int tid   = threadIdx.x;
    const int lane  = tid & 31;
    const int warp  = tid >> 5;

    // ---- prologue: stage durations, EXACT sequential fp32 cumsum (thread 0) ----
    for (int i = tid; i < KK; i += THREADS) sPh[i] = durations[b * KK + i];
    if (tid == 0) { sKb[0] = KK; sKb[1] = 0; }
    for (int i = tid; i < WMAX * WP; i += THREADS) sW[i] = 0.0f;
    __syncthreads();
    if (tid == 0) {
        float s = 0.0f;
        #pragma unroll 8
        for (int k = 0; k < KK; ++k) {
            float dk = sPh[k];
            s += dk;                       // strictly sequential association
            sC[k] = s - 0.5f * dk;
        }
    }
    __syncthreads();

    // ---- phase 1: binary-search window + windowed softmax, QUAD-UNION layout ----
    if (tid < TTILE) {                     // 4 full warps; quads = 4 consecutive lanes
        const int tt = tid;
        const float tc = (float)(t0 + tt) + 0.5f;
        int pos = 0;                       // count of centers < tc (ascending)
        #pragma unroll
        for (int step = 256; step; step >>= 1) {
            int np = pos + step;
            if (np <= KK && sC[np - 1] < tc) pos = np;
        }
        int ka = pos > 0 ? pos - 1 : 0;
        int kz = pos < KK ? pos : KK - 1;
        float da = fabsf(tc - sC[ka]);
        float db = fabsf(tc - sC[kz]);
        int kc; float dmin;
        if (da <= db) { kc = ka; dmin = da; } else { kc = kz; dmin = db; }
        const float m = -(dmin * dmin);    // max energy (dist^2 unimodal in k)
        const float nthr = m - THRESH;
        int kmn = kc, kmx = kc;
        while (kmn > 0) {                  // qualifying set is contiguous
            float df = tc - sC[kmn - 1];
            if (-(df * df) > nthr) --kmn; else break;
        }
        while (kmx < KK - 1) {
            float df = tc - sC[kmx + 1];
            if (-(df * df) > nthr) ++kmx; else break;
        }
        // quad base: min kmn over the 4 frames of this quad (lanes 4a..4a+3)
        int qmin = kmn;
        qmin = min(qmin, __shfl_xor_sync(0xffffffffu, qmin, 1));
        qmin = min(qmin, __shfl_xor_sync(0xffffffffu, qmin, 2));
        const int ksh = kmn - qmin;        // this frame's shift within the union
        int wid = kmx - kmn + 1;
        if (wid > WMAX - ksh) wid = WMAX - ksh;   // clamp (never binds in practice)

        float sum = 0.0f;
        for (int j = 0; j < wid; ++j) {
            float df = tc - sC[kmn + j];
            float x = __expf(-(df * df) - m);
            sW[(ksh + j) * WP + tt] = x;   // union-coordinate slot
            sum += x;
        }
        const float inv = 1.0f / sum;
        for (int j = 0; j < wid; ++j) sW[(ksh + j) * WP + tt] *= inv;

        int uw = ksh + wid;                // union width contribution
        uw = max(uw, __shfl_xor_sync(0xffffffffu, uw, 1));
        uw = max(uw, __shfl_xor_sync(0xffffffffu, uw, 2));
        if ((tt & 3) == 0) {
            sQ[tt >> 2] = qmin;
            sUW[tt >> 2] = uw;
        }
        atomicMin(&sKb[0], kmn);
        atomicMax(&sKb[1], kmx);
    }
    __syncthreads();

    const int kb = sKb[0];
    int span = sKb[1] - kb + 1;
    if (span > SPAN) span = SPAN;          // safety clamp (never triggers here)

    // ---- phase 2: bulk-stage the block's phoneme panel (coalesced, high MLP) ----
    for (int r = warp; r < DHALF; r += NWARP) {
        const float* prow = phoneme + ((size_t)b * DD + dbase + r) * KK + kb;
        int c0 = lane, c1 = lane + 32;
        float* dst = sPh + r * SPANP;
        dst[c0] = (c0 < span) ? prow[c0] : 0.0f;
        dst[c1] = (c1 < span) ? prow[c1] : 0.0f;
        if (lane < SPANP - SPAN) dst[SPAN + lane] = 0.0f;   // pad tail
    }
    __syncthreads();

    // ---- phase 3: quad-union contraction — ONE phoneme value feeds 4 frames ----
    const int tbase = 4 * lane;
    const int qq = min(sQ[lane] - kb, SPAN - 1);   // quad's phoneme base in panel
    const int wm = sUW[lane];                      // quad union width (typ. 3-6)

    const int dw = warp * DPW;
    const size_t fo = ((size_t)b * DD + dbase) * TT + t0 + tbase;
    const float* frp = frame + fo;
    float* op = out + fo;

    // depth-2 (pair) frame prefetch
    float4 fA = *(const float4*)(frp + (size_t)dw * TT);
    float4 fB = *(const float4*)(frp + (size_t)(dw + 1) * TT);

    #pragma unroll 1
    for (int i = 0; i < DPW; i += 2) {
        const float* pr0 = sPh + (dw + i) * SPANP + qq;
        const float* pr1 = pr0 + SPANP;
        float4 f0 = fA, f1 = fB;
        if (i + 2 < DPW) {
            fA = *(const float4*)(frp + (size_t)(dw + i + 2) * TT);
            fB = *(const float4*)(frp + (size_t)(dw + i + 3) * TT);
        }

        float ax0 = 0.f, ay0 = 0.f, az0 = 0.f, aw0 = 0.f;
        float ax1 = 0.f, ay1 = 0.f, az1 = 0.f, aw1 = 0.f;
        #pragma unroll 1
        for (int j = 0; j < wm; ++j) {     // adaptive trip count
            float4 w4 = *(const float4*)(sW + j * WP + tbase);
            float p0 = pr0[j];             // shared by all 4 frames of the quad
            float p1 = pr1[j];
            ax0 = fmaf(w4.x, p0, ax0);
            ay0 = fmaf(w4.y, p0, ay0);
            az0 = fmaf(w4.z, p0, az0);
            aw0 = fmaf(w4.w, p0, aw0);
            ax1 = fmaf(w4.x, p1, ax1);
            ay1 = fmaf(w4.y, p1, ay1);
            az1 = fmaf(w4.z, p1, az1);
            aw1 = fmaf(w4.w, p1, aw1);
        }
        *(float4*)(op + (size_t)(dw + i) * TT) =
            make_float4(f0.x + ax0, f0.y + ay0, f0.z + az0, f0.w + aw0);
        *(float4*)(op + (size_t)(dw + i + 1) * TT) =
            make_float4(f1.x + ax1, f1.y + ay1, f1.z + az1, f1.w + aw1);
    }
}

extern "C" void kernel_launch(void* const* d_in, const int* in_sizes, int n_in,
                              void* d_out, int out_size) {
    const float* durations = (const float*)d_in[0];  // (B, K)
    const float* phoneme   = (const float*)d_in[1];  // (B, D, K)
    const float* frame     = (const float*)d_in[2];  // (B, D, T)
    float* out = (float*)d_out;                      // (B, D, T)

    size_t smem = (size_t)(KK + WMAX * WP + DHALF * SPANP) * sizeof(float)
                + (size_t)(TTILE / 4 * 2 + 2) * sizeof(int);
    cudaFuncSetAttribute(fused_upsample_kernel,
                         cudaFuncAttributeMaxDynamicSharedMemorySize, (int)smem);
    dim3 grid(TT / TTILE, BB, DD / DHALF);
    fused_upsample_kernel<<<grid, THREADS, smem>>>(durations, phoneme, frame, out);
}

// round 14
// speedup vs baseline: 1.0525x; 1.0525x over previous
#include <cuda_runtime.h>

#define BB 16
#define KK 512
#define DD 256
#define TT 4096
#define TTILE 128          // frames per block
#define DHALF 64           // d-rows per block (D split over grid.z=4)
#define NWARP 8
#define THREADS 256
#define DPW (DHALF / NWARP)  // 8 d-rows per warp
#define SPAN 64            // max block k-range staged
#define SPANP 80           // sPh row pitch: SPAN + WMAX zero-pad
#define WMAX 16            // max weight slots per quad-union window
#define WP 132             // sW row pitch (floats): 16B multiple + bank offset
#define THRESH 25.0f       // keep terms with weight ratio > e^-25

__global__ void __launch_bounds__(THREADS, 5) fused_upsample_kernel(
    const float* __restrict__ durations,  // (B, K)
    const float* __restrict__ phoneme,    // (B, D, K)
    const float* __restrict__ frame,      // (B, D, T)
    float* __restrict__ out)              // (B, D, T)
{
    extern __shared__ __align__(16) float sm[];
    float* sC  = sm;                              // KK centers
    float* sW  = sC + KK;                         // WMAX * WP   ([union j][t] weights)
    float* sPh = sW + WMAX * WP;                  // DHALF * SPANP (also cumsum scratch)
    int* sQ    = (int*)(sPh + DHALF * SPANP);     // TTILE/4 quad base (absolute kmn)
    int* sUW   = sQ + TTILE / 4;                  // TTILE/4 quad union width
    int* sKb   = sUW + TTILE / 4;                 // 2

    const int b     = blockIdx.y;
    const int t0    = blockIdx.x * TTILE;
    const int dbase = blockIdx.z * DHALF;
    const int tid   = threadIdx.x;
    const int lane  = tid & 31;
    const int warp  = tid >> 5;

    // ---- prologue: stage durations, EXACT sequential fp32 cumsum (thread 0) ----
    for (int i = tid; i < KK; i += THREADS) sPh[i] = durations[b * KK + i];
    if (tid == 0) { sKb[0] = KK; sKb[1] = 0; }
    for (int i = tid; i < WMAX * WP; i += THREADS) sW[i] = 0.0f;
    __syncthreads();
    if (tid == 0) {
        float s = 0.0f;
        #pragma unroll 8
        for (int k = 0; k < KK; ++k) {
            float dk = sPh[k];
            s += dk;                       // strictly sequential association
            sC[k] = s - 0.5f * dk;
        }
    }
    __syncthreads();

    // ---- phase 1: binary-search window + windowed softmax, QUAD-UNION layout ----
    if (tid < TTILE) {                     // 4 full warps; quads = 4 consecutive lanes
        const int tt = tid;
        const float tc = (float)(t0 + tt) + 0.5f;
        int pos = 0;                       // count of centers < tc (ascending)
        #pragma unroll
        for (int step = 256; step; step >>= 1) {
            int np = pos + step;
            if (np <= KK && sC[np - 1] < tc) pos = np;
        }
        int ka = pos > 0 ? pos - 1 : 0;
        int kz = pos < KK ? pos : KK - 1;
        float da = fabsf(tc - sC[ka]);
        float db = fabsf(tc - sC[kz]);
        int kc; float dmin;
        if (da <= db) { kc = ka; dmin = da; } else { kc = kz; dmin = db; }
        const float m = -(dmin * dmin);    // max energy (dist^2 unimodal in k)
        const float nthr = m - THRESH;
        int kmn = kc, kmx = kc;
        while (kmn > 0) {                  // qualifying set is contiguous
            float df = tc - sC[kmn - 1];
            if (-(df * df) > nthr) --kmn; else break;
        }
        while (kmx < KK - 1) {
            float df = tc - sC[kmx + 1];
            if (-(df * df) > nthr) ++kmx; else break;
        }
        // quad base: min kmn over the 4 frames of this quad (lanes 4a..4a+3)
        int qmin = kmn;
        qmin = min(qmin, __shfl_xor_sync(0xffffffffu, qmin, 1));
        qmin = min(qmin, __shfl_xor_sync(0xffffffffu, qmin, 2));
        const int ksh = kmn - qmin;        // this frame's shift within the union
        int wid = kmx - kmn + 1;
        if (wid > WMAX - ksh) wid = WMAX - ksh;   // clamp (never binds in practice)

        float sum = 0.0f;
        for (int j = 0; j < wid; ++j) {
            float df = tc - sC[kmn + j];
            float x = __expf(-(df * df) - m);
            sW[(ksh + j) * WP + tt] = x;   // union-coordinate slot
            sum += x;
        }
        const float inv = 1.0f / sum;
        for (int j = 0; j < wid; ++j) sW[(ksh + j) * WP + tt] *= inv;

        int uw = ksh + wid;                // union width contribution
        uw = max(uw, __shfl_xor_sync(0xffffffffu, uw, 1));
        uw = max(uw, __shfl_xor_sync(0xffffffffu, uw, 2));
        if ((tt & 3) == 0) {
            sQ[tt >> 2] = qmin;
            sUW[tt >> 2] = uw;
        }
        atomicMin(&sKb[0], kmn);
        atomicMax(&sKb[1], kmx);
    }
    __syncthreads();

    const int kb = sKb[0];
    int span = sKb[1] - kb + 1;
    if (span > SPAN) span = SPAN;          // safety clamp (never triggers here)

    // ---- phase 2: bulk-stage the block's phoneme panel (coalesced, high MLP) ----
    for (int r = warp; r < DHALF; r += NWARP) {
        const float* prow = phoneme + ((size_t)b * DD + dbase + r) * KK + kb;
        int c0 = lane, c1 = lane + 32;
        float* dst = sPh + r * SPANP;
        dst[c0] = (c0 < span) ? prow[c0] : 0.0f;
        dst[c1] = (c1 < span) ? prow[c1] : 0.0f;
        if (lane < SPANP - SPAN) dst[SPAN + lane] = 0.0f;   // pad tail
    }
    __syncthreads();

    // ---- phase 3: quad-union contraction — ONE phoneme value feeds 4 frames ----
    const int tbase = 4 * lane;
    const int qq = min(sQ[lane] - kb, SPAN - 1);   // quad's phoneme base in panel
    const int wm = sUW[lane];                      // quad union width (typ. 3-6)

    const int dw = warp * DPW;
    const size_t fo = ((size_t)b * DD + dbase) * TT + t0 + tbase;
    const float* frp = frame + fo;
    float* op = out + fo;

    // depth-2 (pair) frame prefetch
    float4 fA = *(const float4*)(frp + (size_t)dw * TT);
    float4 fB = *(const float4*)(frp + (size_t)(dw + 1) * TT);

    #pragma unroll 1
    for (int i = 0; i < DPW; i += 2) {
        const float* pr0 = sPh + (dw + i) * SPANP + qq;
        const float* pr1 = pr0 + SPANP;
        float4 f0 = fA, f1 = fB;
        if (i + 2 < DPW) {
            fA = *(const float4*)(frp + (size_t)(dw + i + 2) * TT);
            fB = *(const float4*)(frp + (size_t)(dw + i + 3) * TT);
        }

        float ax0 = 0.f, ay0 = 0.f, az0 = 0.f, aw0 = 0.f;
        float ax1 = 0.f, ay1 = 0.f, az1 = 0.f, aw1 = 0.f;
        #pragma unroll 1
        for (int j = 0; j < wm; ++j) {     // adaptive trip count
            float4 w4 = *(const float4*)(sW + j * WP + tbase);
            float p0 = pr0[j];             // shared by all 4 frames of the quad
            float p1 = pr1[j];
            ax0 = fmaf(w4.x, p0, ax0);
            ay0 = fmaf(w4.y, p0, ay0);
            az0 = fmaf(w4.z, p0, az0);
            aw0 = fmaf(w4.w, p0, aw0);
            ax1 = fmaf(w4.x, p1, ax1);
            ay1 = fmaf(w4.y, p1, ay1);
            az1 = fmaf(w4.z, p1, az1);
            aw1 = fmaf(w4.w, p1, aw1);
        }
        *(float4*)(op + (size_t)(dw + i) * TT) =
            make_float4(f0.x + ax0, f0.y + ay0, f0.z + az0, f0.w + aw0);
        *(float4*)(op + (size_t)(dw + i + 1) * TT) =
            make_float4(f1.x + ax1, f1.y + ay1, f1.z + az1, f1.w + aw1);
    }
}

extern "C" void kernel_launch(void* const* d_in, const int* in_sizes, int n_in,
                              void* d_out, int out_size) {
    const float* durations = (const float*)d_in[0];  // (B, K)
    const float* phoneme   = (const float*)d_in[1];  // (B, D, K)
    const float* frame     = (const float*)d_in[2];  // (B, D, T)
    float* out = (float*)d_out;                      // (B, D, T)

    size_t smem = (size_t)(KK + WMAX * WP + DHALF * SPANP) * sizeof(float)
                + (size_t)(TTILE / 4 * 2 + 2) * sizeof(int);
    cudaFuncSetAttribute(fused_upsample_kernel,
                         cudaFuncAttributeMaxDynamicSharedMemorySize, (int)smem);
    dim3 grid(TT / TTILE, BB, DD / DHALF);
    fused_upsample_kernel<<<grid, THREADS, smem>>>(durations, phoneme, frame, out);
}

// round 16
// speedup vs baseline: 1.2390x; 1.1772x over previous
#include <cuda_runtime.h>

#define BB 16
#define KK 512
#define DD 256
#define TT 4096
#define TTILE 128          // frames per block
#define DHALF 64           // d-rows per block (D split over grid.z=4)
#define NWARP 8
#define THREADS 256
#define DPW (DHALF / NWARP)  // 8 d-rows per warp
#define SPAN 64            // max block k-range staged
#define SPANP 80           // sPh row pitch: SPAN + WMAX zero-pad
#define WMAX 16            // max weight slots per quad-union window
#define WP 132             // sW row pitch (floats): 16B multiple + bank offset
#define THRESH 25.0f       // keep terms with weight ratio > e^-25
#define DLIM 20.0f         // conservative window radius for panel bounds
#define IMARG 6            // index margin on panel bounds

__device__ __forceinline__ int lb512(const float* a, float v) {
    int p = 0;                         // count of elements < v (a ascending)
    #pragma unroll
    for (int s = 256; s; s >>= 1) {
        int np = p + s;
        if (np <= KK && a[np - 1] < v) p = np;
    }
    return p;
}

__global__ void __launch_bounds__(THREADS, 5) fused_upsample_kernel(
    const float* __restrict__ durations,  // (B, K)
    const float* __restrict__ phoneme,    // (B, D, K)
    const float* __restrict__ frame,      // (B, D, T)
    float* __restrict__ out)              // (B, D, T)
{
    extern __shared__ __align__(16) float sm[];
    float* sC   = sm;                             // KK exact centers
    float* sDur = sC + KK;                        // KK staged durations
    float* sCa  = sDur + KK;                      // KK approx centers (bounds only)
    float* sW   = sCa + KK;                       // WMAX * WP  ([union j][t] weights)
    float* sPh  = sW + WMAX * WP;                 // DHALF * SPANP phoneme panel
    int* sQ  = (int*)(sPh + DHALF * SPANP);       // TTILE/4 quad base (absolute kmn)
    int* sUW = sQ + TTILE / 4;                    // TTILE/4 quad union width
    int* sB  = sUW + TTILE / 4;                   // {kb_est, span_est}

    const int b     = blockIdx.y;
    const int t0    = blockIdx.x * TTILE;
    const int dbase = blockIdx.z * DHALF;
    const int tid   = threadIdx.x;
    const int lane  = tid & 31;
    const int warp  = tid >> 5;

    // stage durations (coalesced)
    for (int i = tid; i < KK; i += THREADS) sDur[i] = durations[b * KK + i];
    __syncthreads();

    // ---- overlapped prologue ----
    if (warp == 0) {
        if (lane == 0) {                 // EXACT sequential fp32 cumsum (unchanged)
            float s = 0.0f;
            #pragma unroll 8
            for (int k = 0; k < KK; ++k) {
                float dk = sDur[k];
                s += dk;                 // strictly sequential association
                sC[k] = s - 0.5f * dk;
            }
        }
    } else {
        if (warp == 1) {
            // approximate scan for BOUNDS ONLY: lane owns 16 consecutive elems
            float loc[16];
            float part = 0.0f;
            #pragma unroll
            for (int j = 0; j < 16; ++j) { loc[j] = sDur[lane * 16 + j]; part += loc[j]; }
            // canonical Hillis-Steele inclusive scan of lane partials
            float incl = part;
            #pragma unroll
            for (int o = 1; o < 32; o <<= 1) {
                float v = __shfl_up_sync(0xffffffffu, incl, o);
                if (lane >= o) incl += v;
            }
            float run = incl - part;     // exclusive prefix for this lane
            #pragma unroll
            for (int j = 0; j < 16; ++j) {
                run += loc[j];
                sCa[lane * 16 + j] = run - 0.5f * loc[j];
            }
            __syncwarp();
            if (lane == 0) {             // conservative panel bounds from sCa
                const float tlo = (float)t0 + 0.5f;
                const float thi = (float)(t0 + TTILE) - 0.5f;
                int lo = lb512(sCa, tlo - DLIM);
                int hi = lb512(sCa, thi + DLIM);        // first idx >= thi+DLIM
                int nlo = lb512(sCa, tlo);              // nearest-to-start vicinity
                int nhi = lb512(sCa, thi);              // nearest-to-end vicinity
                lo = min(lo, nlo - 1) - IMARG;
                hi = max(hi, nhi) + IMARG;
                if (lo < 0) lo = 0;
                if (hi > KK - 1) hi = KK - 1;
                int span = hi - lo + 1;
                if (span > SPAN) span = SPAN;
                sB[0] = lo;
                sB[1] = span;
            }
        } else {
            // warps 2-7 zero the weight table
            for (int i = (tid - 64); i < WMAX * WP; i += 192) sW[i] = 0.0f;
        }
        asm volatile("bar.sync 1, 224;" ::: "memory");   // warps 1..7 only

        // panel staging (overlaps warp 0's serial chain)
        const int kb_e = sB[0];
        const int sp_e = sB[1];
        for (int r = warp - 1; r < DHALF; r += 7) {
            const float* prow = phoneme + ((size_t)b * DD + dbase + r) * KK + kb_e;
            float* dst = sPh + r * SPANP;
            int c0 = lane, c1 = lane + 32;
            dst[c0] = (c0 < sp_e) ? prow[c0] : 0.0f;
            dst[c1] = (c1 < sp_e) ? prow[c1] : 0.0f;
            if (lane < SPANP - SPAN) dst[SPAN + lane] = 0.0f;   // pad tail
        }
    }
    __syncthreads();

    // ---- phase 1: binary-search window + windowed softmax, QUAD-UNION layout ----
    if (tid < TTILE) {                   // 4 warps; quads = 4 consecutive lanes
        const int tt = tid;
        const float tc = (float)(t0 + tt) + 0.5f;
        int pos = lb512(sC, tc);
        int ka = pos > 0 ? pos - 1 : 0;
        int kz = pos < KK ? pos : KK - 1;
        float da = fabsf(tc - sC[ka]);
        float db = fabsf(tc - sC[kz]);
        int kc; float dmin;
        if (da <= db) { kc = ka; dmin = da; } else { kc = kz; dmin = db; }
        const float m = -(dmin * dmin);  // max energy (dist^2 unimodal in k)
        const float nthr = m - THRESH;
        int kmn = kc, kmx = kc;
        while (kmn > 0) {                // qualifying set is contiguous
            float df = tc - sC[kmn - 1];
            if (-(df * df) > nthr) --kmn; else break;
        }
        while (kmx < KK - 1) {
            float df = tc - sC[kmx + 1];
            if (-(df * df) > nthr) ++kmx; else break;
        }
        int qmin = kmn;                  // quad base over lanes 4a..4a+3
        qmin = min(qmin, __shfl_xor_sync(0xffffffffu, qmin, 1));
        qmin = min(qmin, __shfl_xor_sync(0xffffffffu, qmin, 2));
        const int ksh = kmn - qmin;
        int wid = kmx - kmn + 1;
        if (wid > WMAX - ksh) wid = WMAX - ksh;

        float sum = 0.0f;
        for (int j = 0; j < wid; ++j) {
            float df = tc - sC[kmn + j];
            float x = __expf(-(df * df) - m);
            sW[(ksh + j) * WP + tt] = x;
            sum += x;
        }
        const float inv = 1.0f / sum;
        for (int j = 0; j < wid; ++j) sW[(ksh + j) * WP + tt] *= inv;

        int uw = ksh + wid;
        uw = max(uw, __shfl_xor_sync(0xffffffffu, uw, 1));
        uw = max(uw, __shfl_xor_sync(0xffffffffu, uw, 2));
        if ((tt & 3) == 0) {
            sQ[tt >> 2] = qmin;
            sUW[tt >> 2] = uw;
        }
    }
    __syncthreads();

    // ---- phase 3: quad-union contraction — ONE phoneme value feeds 4 frames ----
    const int kb = sB[0];
    const int tbase = 4 * lane;
    int qq = sQ[lane] - kb;              // quad base within the staged panel
    qq = max(min(qq, SPAN - 1), 0);      // safety clamp (miss weight ~e^-25)
    const int wm = sUW[lane];            // quad union width (typ. 2-5)

    const int dw = warp * DPW;
    const size_t fo = ((size_t)b * DD + dbase) * TT + t0 + tbase;
    const float* frp = frame + fo;
    float* op = out + fo;

    float4 fA = *(const float4*)(frp + (size_t)dw * TT);
    float4 fB = *(const float4*)(frp + (size_t)(dw + 1) * TT);

    #pragma unroll 1
    for (int i = 0; i < DPW; i += 2) {
        const float* pr0 = sPh + (dw + i) * SPANP + qq;
        const float* pr1 = pr0 + SPANP;
        float4 f0 = fA, f1 = fB;
        if (i + 2 < DPW) {
            fA = *(const float4*)(frp + (size_t)(dw + i + 2) * TT);
            fB = *(const float4*)(frp + (size_t)(dw + i + 3) * TT);
        }

        float ax0 = 0.f, ay0 = 0.f, az0 = 0.f, aw0 = 0.f;
        float ax1 = 0.f, ay1 = 0.f, az1 = 0.f, aw1 = 0.f;
        #pragma unroll 1
        for (int j = 0; j < wm; ++j) {
            float4 w4 = *(const float4*)(sW + j * WP + tbase);
            float p0 = pr0[j];
            float p1 = pr1[j];
            ax0 = fmaf(w4.x, p0, ax0);
            ay0 = fmaf(w4.y, p0, ay0);
            az0 = fmaf(w4.z, p0, az0);
            aw0 = fmaf(w4.w, p0, aw0);
            ax1 = fmaf(w4.x, p1, ax1);
            ay1 = fmaf(w4.y, p1, ay1);
            az1 = fmaf(w4.z, p1, az1);
            aw1 = fmaf(w4.w, p1, aw1);
        }
        *(float4*)(op + (size_t)(dw + i) * TT) =
            make_float4(f0.x + ax0, f0.y + ay0, f0.z + az0, f0.w + aw0);
        *(float4*)(op + (size_t)(dw + i + 1) * TT) =
            make_float4(f1.x + ax1, f1.y + ay1, f1.z + az1, f1.w + aw1);
    }
}

extern "C" void kernel_launch(void* const* d_in, const int* in_sizes, int n_in,
                              void* d_out, int out_size) {
    const float* durations = (const float*)d_in[0];  // (B, K)
    const float* phoneme   = (const float*)d_in[1];  // (B, D, K)
    const float* frame     = (const float*)d_in[2];  // (B, D, T)
    float* out = (float*)d_out;                      // (B, D, T)

    size_t smem = (size_t)(3 * KK + WMAX * WP + DHALF * SPANP) * sizeof(float)
                + (size_t)(TTILE / 4 * 2 + 2) * sizeof(int);
    cudaFuncSetAttribute(fused_upsample_kernel,
                         cudaFuncAttributeMaxDynamicSharedMemorySize, (int)smem);
    dim3 grid(TT / TTILE, BB, DD / DHALF);
    fused_upsample_kernel<<<grid, THREADS, smem>>>(durations, phoneme, frame, out);
}